// round 12
// baseline (speedup 1.0000x reference)
#include <cuda_runtime.h>
#include <cuda_bf16.h>
#include <math.h>

#define CN 128
#define SS 56
#define NTAP 36
#define PROWS 61          // padded rows: y in [-2, 58]
#define PITCH 65          // padded col pitch
#define USPLIT 8
#define UCH (CN / USPLIT) // 16 u-values per block -> 8 pairs
#define NPAIR (UCH / 2)
#define NT 224            // 28 row-pairs x 8 strips of 7 cols
#define PLANEF 7936       // floats per pair plane (61*65*2 = 7930, padded to 128B mult)

// ---------------------------------------------------------------------------
// intrinsics
// ---------------------------------------------------------------------------
__device__ __forceinline__ float fast_lg2(float v) {
    float r; asm("lg2.approx.f32 %0, %1;" : "=f"(r) : "f"(v)); return r;
}
__device__ __forceinline__ float fast_ex2(float v) {
    float r; asm("ex2.approx.f32 %0, %1;" : "=f"(r) : "f"(v)); return r;
}
__device__ __forceinline__ unsigned long long lds64(unsigned addr) {
    unsigned long long r;
    asm volatile("ld.shared.b64 %0, [%1];" : "=l"(r) : "r"(addr));
    return r;
}
__device__ __forceinline__ void sts64(unsigned addr, unsigned long long v) {
    asm volatile("st.shared.b64 [%0], %1;" :: "r"(addr), "l"(v) : "memory");
}
// packed dual-FMA: d.lo += a.lo*b.lo ; d.hi += a.hi*b.hi
__device__ __forceinline__ void fma2(unsigned long long& d,
                                     unsigned long long a,
                                     unsigned long long b) {
    asm("fma.rn.f32x2 %0, %1, %2, %0;" : "+l"(d) : "l"(a), "l"(b));
}
__device__ __forceinline__ unsigned long long pack2(float lo, float hi) {
    unsigned long long r;
    asm("mov.b64 %0, {%1, %2};" : "=l"(r) : "f"(lo), "f"(hi));
    return r;
}
__device__ __forceinline__ float2 unpack2(unsigned long long v) {
    float2 r;
    asm("mov.b64 {%0, %1}, %2;" : "=f"(r.x), "=f"(r.y) : "l"(v));
    return r;
}

// scratch (allocation-free rule: __device__ globals)
__device__ float d_bank[CN * CN * NTAP];   // g[i][u][t]
__device__ float d_biasn[CN];              // bias^nU
__device__ float d_partial[USPLIT][2 * CN * SS * SS];

// ---------------------------------------------------------------------------
// Kernel 1: precompute gaussian bank + bias^nU
// ---------------------------------------------------------------------------
__global__ void bank_kernel(const float* __restrict__ theta,
                            const float* __restrict__ p,
                            const float* __restrict__ sig,
                            const float* __restrict__ a,
                            const float* __restrict__ bias,
                            const float* __restrict__ nU) {
    int i = blockIdx.x;
    int u = threadIdx.x;
    int iu = i * CN + u;
    float th = theta[iu];
    float pv = p[iu];
    float sg = sig[iu];
    float av = a[iu];
    float st, ct;
    sincosf(th, &st, &ct);   // theta up to ~300 rad -> precise path required
    float amp = av / (2.0f * 3.14159265358979323846f * pv * sg);
    float ip2 = 1.0f / (pv * pv);
    float is2 = 1.0f / (sg * sg);
    float* out = &d_bank[iu * NTAP];
    #pragma unroll
    for (int r = 0; r < 6; r++) {
        float xv = -3.0f + 1.2f * (float)r;
        #pragma unroll
        for (int c = 0; c < 6; c++) {
            float yv = -3.0f + 1.2f * (float)c;
            float xr = xv * ct + yv * st;
            float yr = -xv * st + yv * ct;
            out[r * 6 + c] = amp * expf(-0.5f * (xr * xr * ip2 + yr * yr * is2));
        }
    }
    if (u == 0) d_biasn[i] = powf(bias[i], nU[i]);
}

// ---------------------------------------------------------------------------
// Kernel 2: main — double-buffered u-pair FFMA2 conv, 2x7 tile per thread
// grid: (B*CN, USPLIT); block: 224 threads = 28 row-pairs x 8 strips
// dynamic smem: 2 pair planes + weights
// ---------------------------------------------------------------------------
__global__ __launch_bounds__(NT, 3) void main_kernel(const float* __restrict__ x,
                                                     const float* __restrict__ nI) {
    extern __shared__ float smem[];
    float* sP0 = smem;                    // plane 0
    float* sP1 = smem + PLANEF;           // plane 1
    float* sG2 = smem + 2 * PLANEF;       // NPAIR*NTAP*2 interleaved weights
    float* sN  = sG2 + NPAIR * NTAP * 2;  // UCH exponents

    const int bi = blockIdx.x;          // b*CN + i
    const int uc = blockIdx.y;          // u chunk
    const int i  = bi & (CN - 1);
    const int tid = threadIdx.x;

    const unsigned p0_base = (unsigned)__cvta_generic_to_shared(sP0);
    const unsigned p1_base = (unsigned)__cvta_generic_to_shared(sP1);
    const unsigned sg2_base = (unsigned)__cvta_generic_to_shared(sG2);

    // zero both pair planes (pads stay 0 forever)
    for (int idx = tid; idx < 2 * PLANEF; idx += NT) smem[idx] = 0.0f;

    // gaussian weights for this u-chunk, interleaved by pair
    const float* gb = d_bank + (i * CN + uc * UCH) * NTAP;
    for (int idx = tid; idx < UCH * NTAP; idx += NT) {
        int u = idx / NTAP;
        int t = idx - u * NTAP;
        sG2[(u >> 1) * (NTAP * 2) + t * 2 + (u & 1)] = gb[idx];
    }
    if (tid < UCH) sN[tid] = nI[i * CN + uc * UCH + tid];

    const int rp    = tid >> 3;          // 0..27  -> out rows 2rp, 2rp+1
    const int strip = tid & 7;           // 0..7   -> out cols strip*7 ..+6
    const int r0 = 2 * rp;
    const int x0 = strip * 7;

    // per-thread log2(x) over its own 2x7 tile, in registers
    const float* xr = x + bi * (SS * SS);
    float Lr[14];
    #pragma unroll
    for (int rr = 0; rr < 2; rr++)
        #pragma unroll
        for (int c = 0; c < 7; c++)
            Lr[rr * 7 + c] = fast_lg2(xr[(r0 + rr) * SS + x0 + c]);

    const unsigned powoff  = 8u * (unsigned)((r0 + 2) * PITCH + x0 + 2); // within plane
    const unsigned convoff = 8u * (unsigned)(r0 * PITCH + x0);

    __syncthreads();                     // zero-fill complete

    // prologue: write pow for pair 0 into plane 0
    {
        float n0 = sN[0], n1 = sN[1];
        #pragma unroll
        for (int rr = 0; rr < 2; rr++)
            #pragma unroll
            for (int c = 0; c < 7; c++) {
                float L = Lr[rr * 7 + c];
                sts64(p0_base + powoff + (unsigned)(rr * PITCH + c) * 8u,
                      pack2(fast_ex2(n0 * L), fast_ex2(n1 * L)));
            }
    }
    __syncthreads();

    unsigned long long accA[7], accB[7];
    #pragma unroll
    for (int o = 0; o < 7; o++) { accA[o] = 0ull; accB[o] = 0ull; }

    #pragma unroll
    for (int pp = 0; pp < NPAIR; pp++) {
        const unsigned cur_base  = (pp & 1) ? p1_base : p0_base;
        const unsigned next_base = (pp & 1) ? p0_base : p1_base;

        // conv over plane cur (g-row register caching: each weight loaded once)
        const unsigned gwb = sg2_base + (unsigned)(pp * NTAP * 2) * 4u;
        unsigned long long gprev[6];
        #pragma unroll
        for (int ir = 0; ir < 7; ir++) {   // input padded rows r0 .. r0+6
            unsigned wb = cur_base + convoff + (unsigned)(ir * PITCH) * 8u;
            unsigned long long w[12];      // sliding window pairs
            #pragma unroll
            for (int j = 0; j < 12; j++) w[j] = lds64(wb + 8u * j);
            unsigned long long gcur[6];
            if (ir < 6) {
                #pragma unroll
                for (int kx = 0; kx < 6; kx++) {
                    gcur[kx] = lds64(gwb + 8u * (ir * 6 + kx));
                    #pragma unroll
                    for (int o = 0; o < 7; o++) fma2(accA[o], w[o + kx], gcur[kx]);
                }
            }
            if (ir >= 1) {                 // out row r0+1, kernel row ir-1
                #pragma unroll
                for (int kx = 0; kx < 6; kx++) {
                    #pragma unroll
                    for (int o = 0; o < 7; o++) fma2(accB[o], w[o + kx], gprev[kx]);
                }
            }
            #pragma unroll
            for (int kx = 0; kx < 6; kx++) gprev[kx] = gcur[kx];
        }

        // overlap: write next pair's pow into the other plane (hidden under FFMA)
        if (pp + 1 < NPAIR) {
            float n0 = sN[2 * (pp + 1)];
            float n1 = sN[2 * (pp + 1) + 1];
            #pragma unroll
            for (int rr = 0; rr < 2; rr++)
                #pragma unroll
                for (int c = 0; c < 7; c++) {
                    float L = Lr[rr * 7 + c];
                    sts64(next_base + powoff + (unsigned)(rr * PITCH + c) * 8u,
                          pack2(fast_ex2(n0 * L), fast_ex2(n1 * L)));
                }
        }
        __syncthreads();                   // single barrier per pair
    }

    float* outp = &d_partial[uc][bi * (SS * SS) + r0 * SS + x0];
    #pragma unroll
    for (int o = 0; o < 7; o++) {
        float2 va = unpack2(accA[o]);
        float2 vb = unpack2(accB[o]);
        outp[o]      = va.x + va.y;
        outp[SS + o] = vb.x + vb.y;
    }
}

// ---------------------------------------------------------------------------
// Kernel 3: combine — out = x^nU / (bias^nU + sum of partials)
// ---------------------------------------------------------------------------
__global__ void combine_kernel(const float* __restrict__ x,
                               const float* __restrict__ nU,
                               float* __restrict__ out, int total) {
    int idx = blockIdx.x * blockDim.x + threadIdx.x;
    if (idx >= total) return;
    int i = (idx / (SS * SS)) & (CN - 1);
    float d = d_biasn[i];
    #pragma unroll
    for (int s = 0; s < USPLIT; s++) d += d_partial[s][idx];
    float num = fast_ex2(nU[i] * fast_lg2(x[idx]));
    out[idx] = num / d;
}

// ---------------------------------------------------------------------------
extern "C" void kernel_launch(void* const* d_in, const int* in_sizes, int n_in,
                              void* d_out, int out_size) {
    const float* x     = (const float*)d_in[0];
    const float* theta = (const float*)d_in[1];
    const float* p     = (const float*)d_in[2];
    const float* sig   = (const float*)d_in[3];
    const float* a     = (const float*)d_in[4];
    const float* nI    = (const float*)d_in[5];
    const float* nU    = (const float*)d_in[6];
    const float* bias  = (const float*)d_in[7];
    float* out = (float*)d_out;

    int B = in_sizes[0] / (CN * SS * SS);   // = 2

    const int smem_bytes = (2 * PLANEF + NPAIR * NTAP * 2 + UCH) * 4;
    cudaFuncSetAttribute(main_kernel, cudaFuncAttributeMaxDynamicSharedMemorySize,
                         smem_bytes);

    bank_kernel<<<CN, CN>>>(theta, p, sig, a, bias, nU);
    main_kernel<<<dim3(B * CN, USPLIT), NT, smem_bytes>>>(x, nI);
    combine_kernel<<<(out_size + 255) / 256, 256>>>(x, nU, out, out_size);
}

// round 13
// speedup vs baseline: 1.6907x; 1.6907x over previous
#include <cuda_runtime.h>
#include <cuda_bf16.h>
#include <math.h>

#define CN 128
#define SS 56
#define NTAP 36
#define PROWS 61          // padded rows: y in [-2, 58]
#define PITCH 65          // padded col pitch
#define USPLIT 8
#define UCH (CN / USPLIT) // 16 u-values per block -> 8 pairs
#define NPAIR (UCH / 2)
#define NT 224            // 28 row-pairs x 8 strips of 7 cols

// ---------------------------------------------------------------------------
// intrinsics
// ---------------------------------------------------------------------------
__device__ __forceinline__ float fast_lg2(float v) {
    float r; asm("lg2.approx.f32 %0, %1;" : "=f"(r) : "f"(v)); return r;
}
__device__ __forceinline__ float fast_ex2(float v) {
    float r; asm("ex2.approx.f32 %0, %1;" : "=f"(r) : "f"(v)); return r;
}
__device__ __forceinline__ unsigned long long lds64(unsigned addr) {
    unsigned long long r;
    asm volatile("ld.shared.b64 %0, [%1];" : "=l"(r) : "r"(addr));
    return r;
}
__device__ __forceinline__ void sts64(unsigned addr, unsigned long long v) {
    asm volatile("st.shared.b64 [%0], %1;" :: "r"(addr), "l"(v) : "memory");
}
// packed dual-FMA: d.lo += a.lo*b.lo ; d.hi += a.hi*b.hi
__device__ __forceinline__ void fma2(unsigned long long& d,
                                     unsigned long long a,
                                     unsigned long long b) {
    asm("fma.rn.f32x2 %0, %1, %2, %0;" : "+l"(d) : "l"(a), "l"(b));
}
__device__ __forceinline__ unsigned long long pack2(float lo, float hi) {
    unsigned long long r;
    asm("mov.b64 %0, {%1, %2};" : "=l"(r) : "f"(lo), "f"(hi));
    return r;
}
__device__ __forceinline__ float2 unpack2(unsigned long long v) {
    float2 r;
    asm("mov.b64 {%0, %1}, %2;" : "=f"(r.x), "=f"(r.y) : "l"(v));
    return r;
}

// scratch (allocation-free rule: __device__ globals)
__device__ float d_bank[CN * CN * NTAP];   // g[i][u][t]
__device__ float d_biasn[CN];              // bias^nU
__device__ float d_partial[USPLIT][2 * CN * SS * SS];

// ---------------------------------------------------------------------------
// Kernel 1: precompute gaussian bank + bias^nU, flattened over (i,u,tap)
// ---------------------------------------------------------------------------
__global__ void bank_kernel(const float* __restrict__ theta,
                            const float* __restrict__ p,
                            const float* __restrict__ sig,
                            const float* __restrict__ a,
                            const float* __restrict__ bias,
                            const float* __restrict__ nU) {
    int g = blockIdx.x * blockDim.x + threadIdx.x;
    if (g >= CN * CN * NTAP) return;
    int iu = g / NTAP;
    int t  = g - iu * NTAP;
    int r = t / 6;
    int c = t - r * 6;

    float th = theta[iu];
    float pv = p[iu];
    float sg = sig[iu];
    float av = a[iu];
    float st, ct;
    sincosf(th, &st, &ct);   // theta up to ~300 rad -> precise path required
    float amp = av / (2.0f * 3.14159265358979323846f * pv * sg);
    float ip2 = 1.0f / (pv * pv);
    float is2 = 1.0f / (sg * sg);

    float xv = -3.0f + 1.2f * (float)r;
    float yv = -3.0f + 1.2f * (float)c;
    float xr = xv * ct + yv * st;
    float yr = -xv * st + yv * ct;
    d_bank[g] = amp * expf(-0.5f * (xr * xr * ip2 + yr * yr * is2));

    if (g < CN) d_biasn[g] = powf(bias[g], nU[g]);
}

// ---------------------------------------------------------------------------
// Kernel 2: main — u-pair packed FFMA2 conv, 2x7 output tile per thread
// grid: (B*CN, USPLIT); block: 224 threads = 28 row-pairs x 8 strips
// (R10 structure: single plane, 2 syncs/pair, static smem; + weight reg cache)
// ---------------------------------------------------------------------------
__global__ __launch_bounds__(NT) void main_kernel(const float* __restrict__ x,
                                                  const float* __restrict__ nI) {
    // interleaved pair plane: (P_u, P_{u+1}) at element idx
    __shared__ float sP2[PROWS * PITCH * 2];
    __shared__ float sG2[NPAIR * NTAP * 2];  // (g_u[t], g_{u+1}[t]) interleaved
    __shared__ float sN[UCH];

    const int bi = blockIdx.x;          // b*CN + i
    const int uc = blockIdx.y;          // u chunk
    const int i  = bi & (CN - 1);
    const int tid = threadIdx.x;

    const unsigned sp2_base = (unsigned)__cvta_generic_to_shared(sP2);
    const unsigned sg2_base = (unsigned)__cvta_generic_to_shared(sG2);

    // zero the pair plane (pads stay 0 forever; interior rewritten each pair)
    for (int idx = tid; idx < PROWS * PITCH * 2; idx += NT) sP2[idx] = 0.0f;

    // gaussian weights for this u-chunk, interleaved by pair
    const float* gb = d_bank + (i * CN + uc * UCH) * NTAP;
    for (int idx = tid; idx < UCH * NTAP; idx += NT) {
        int u = idx / NTAP;
        int t = idx - u * NTAP;
        sG2[(u >> 1) * (NTAP * 2) + t * 2 + (u & 1)] = gb[idx];
    }
    if (tid < UCH) sN[tid] = nI[i * CN + uc * UCH + tid];

    const int rp    = tid >> 3;          // 0..27  -> out rows 2rp, 2rp+1
    const int strip = tid & 7;           // 0..7   -> out cols strip*7 ..+6
    const int r0 = 2 * rp;
    const int x0 = strip * 7;

    // per-thread log2(x) over its own 2x7 tile, kept in registers
    const float* xr = x + bi * (SS * SS);
    float Lr[14];
    #pragma unroll
    for (int rr = 0; rr < 2; rr++)
        #pragma unroll
        for (int c = 0; c < 7; c++)
            Lr[rr * 7 + c] = fast_lg2(xr[(r0 + rr) * SS + x0 + c]);

    // smem byte bases (immediate offsets elsewhere)
    const unsigned powbase  = sp2_base + 8u * (unsigned)((r0 + 2) * PITCH + x0 + 2);
    const unsigned convbase = sp2_base + 8u * (unsigned)(r0 * PITCH + x0);

    unsigned long long accA[7], accB[7];
    #pragma unroll
    for (int o = 0; o < 7; o++) { accA[o] = 0ull; accB[o] = 0ull; }

    for (int pp = 0; pp < NPAIR; pp++) {
        __syncthreads();                 // prev conv reads done before rewrite
        float n0 = sN[2 * pp];
        float n1 = sN[2 * pp + 1];
        #pragma unroll
        for (int rr = 0; rr < 2; rr++)
            #pragma unroll
            for (int c = 0; c < 7; c++) {
                float L = Lr[rr * 7 + c];
                sts64(powbase + (unsigned)(rr * PITCH + c) * 8u,
                      pack2(fast_ex2(n0 * L), fast_ex2(n1 * L)));
            }
        __syncthreads();

        const unsigned gwb = sg2_base + (unsigned)(pp * NTAP * 2) * 4u;
        unsigned long long gprev[6];     // previous kernel-row weights (for accB)
        #pragma unroll
        for (int ir = 0; ir < 7; ir++) {   // input padded rows r0 .. r0+6
            unsigned wb = convbase + (unsigned)(ir * PITCH) * 8u;
            unsigned long long w[12];      // sliding window pairs
            #pragma unroll
            for (int j = 0; j < 12; j++) w[j] = lds64(wb + 8u * j);
            if (ir < 6) {                  // out row r0, kernel row ir
                #pragma unroll
                for (int kx = 0; kx < 6; kx++) {
                    unsigned long long gv = lds64(gwb + 8u * (ir * 6 + kx));
                    #pragma unroll
                    for (int o = 0; o < 7; o++) fma2(accA[o], w[o + kx], gv);
                    if (ir >= 1) {         // out row r0+1, kernel row ir-1
                        #pragma unroll
                        for (int o = 0; o < 7; o++) fma2(accB[o], w[o + kx], gprev[kx]);
                    }
                    gprev[kx] = gv;        // becomes row ir's weight for next iter
                }
            } else {                       // ir == 6: accB only, weights already cached
                #pragma unroll
                for (int kx = 0; kx < 6; kx++) {
                    #pragma unroll
                    for (int o = 0; o < 7; o++) fma2(accB[o], w[o + kx], gprev[kx]);
                }
            }
        }
    }

    float* outp = &d_partial[uc][bi * (SS * SS) + r0 * SS + x0];
    #pragma unroll
    for (int o = 0; o < 7; o++) {
        float2 va = unpack2(accA[o]);
        float2 vb = unpack2(accB[o]);
        outp[o]      = va.x + va.y;
        outp[SS + o] = vb.x + vb.y;
    }
}

// ---------------------------------------------------------------------------
// Kernel 3: combine — out = x^nU / (bias^nU + sum of partials)
// ---------------------------------------------------------------------------
__global__ void combine_kernel(const float* __restrict__ x,
                               const float* __restrict__ nU,
                               float* __restrict__ out, int total) {
    int idx = blockIdx.x * blockDim.x + threadIdx.x;
    if (idx >= total) return;
    int i = (idx / (SS * SS)) & (CN - 1);
    float d = d_biasn[i];
    #pragma unroll
    for (int s = 0; s < USPLIT; s++) d += d_partial[s][idx];
    float num = fast_ex2(nU[i] * fast_lg2(x[idx]));
    out[idx] = num / d;
}

// ---------------------------------------------------------------------------
extern "C" void kernel_launch(void* const* d_in, const int* in_sizes, int n_in,
                              void* d_out, int out_size) {
    const float* x     = (const float*)d_in[0];
    const float* theta = (const float*)d_in[1];
    const float* p     = (const float*)d_in[2];
    const float* sig   = (const float*)d_in[3];
    const float* a     = (const float*)d_in[4];
    const float* nI    = (const float*)d_in[5];
    const float* nU    = (const float*)d_in[6];
    const float* bias  = (const float*)d_in[7];
    float* out = (float*)d_out;

    int B = in_sizes[0] / (CN * SS * SS);   // = 2

    bank_kernel<<<(CN * CN * NTAP + 255) / 256, 256>>>(theta, p, sig, a, bias, nU);
    main_kernel<<<dim3(B * CN, USPLIT), NT>>>(x, nI);
    combine_kernel<<<(out_size + 255) / 256, 256>>>(x, nU, out, out_size);
}

// round 16
// speedup vs baseline: 3.1968x; 1.8908x over previous
#include <cuda_runtime.h>
#include <cuda_bf16.h>
#include <math.h>
#include <stdint.h>

#define CN 128
#define SS 56
#define NPX (SS * SS)          // 3136
#define NTAP 36
#define NT40 40                // padded tap count
#define QPITCH 3200            // padded pixels per Q plane
#define TILE_M 128
#define NTILES 25              // ceil(3136/128)

// ---------------------------------------------------------------------------
// intrinsics
// ---------------------------------------------------------------------------
__device__ __forceinline__ float fast_lg2(float v) {
    float r; asm("lg2.approx.f32 %0, %1;" : "=f"(r) : "f"(v)); return r;
}
__device__ __forceinline__ float fast_ex2(float v) {
    float r; asm("ex2.approx.f32 %0, %1;" : "=f"(r) : "f"(v)); return r;
}
__device__ __forceinline__ unsigned cvt_tf32(float v) {
    unsigned r; asm("cvt.rna.tf32.f32 %0, %1;" : "=r"(r) : "f"(v)); return r;
}
// D(16x8) += A(16x8,row) * B(8x8,col), tf32 inputs, f32 accum
__device__ __forceinline__ void mma8(float* c, const unsigned* a,
                                     unsigned b0, unsigned b1) {
    asm volatile(
        "mma.sync.aligned.m16n8k8.row.col.f32.tf32.tf32.f32 "
        "{%0,%1,%2,%3}, {%4,%5,%6,%7}, {%8,%9}, {%0,%1,%2,%3};"
        : "+f"(c[0]), "+f"(c[1]), "+f"(c[2]), "+f"(c[3])
        : "r"(a[0]), "r"(a[1]), "r"(a[2]), "r"(a[3]), "r"(b0), "r"(b1));
}

// ---------------------------------------------------------------------------
// scratch (device globals are zero-initialized; pads stay 0)
// ---------------------------------------------------------------------------
__device__ float d_bankU[CN * CN * NT40];      // [i][u][t40], t pads = 0
__device__ float d_biasn[CN];
__device__ float d_Q[2 * CN * NT40 * QPITCH];  // Q[bi][t][px], 131 MB

// ---------------------------------------------------------------------------
// Kernel 1: gaussian bank (u-major, t-padded) + bias^nU
// ---------------------------------------------------------------------------
__global__ void bank_kernel(const float* __restrict__ theta,
                            const float* __restrict__ p,
                            const float* __restrict__ sig,
                            const float* __restrict__ a,
                            const float* __restrict__ bias,
                            const float* __restrict__ nU) {
    int g = blockIdx.x * blockDim.x + threadIdx.x;
    if (g >= CN * CN * NTAP) return;
    int iu = g / NTAP;
    int t  = g - iu * NTAP;
    int r = t / 6;
    int c = t - r * 6;

    float th = theta[iu];
    float pv = p[iu];
    float sg = sig[iu];
    float av = a[iu];
    float st, ct;
    sincosf(th, &st, &ct);   // theta up to ~300 rad -> precise path
    float amp = av / (2.0f * 3.14159265358979323846f * pv * sg);
    float ip2 = 1.0f / (pv * pv);
    float is2 = 1.0f / (sg * sg);

    float xv = -3.0f + 1.2f * (float)r;
    float yv = -3.0f + 1.2f * (float)c;
    float xr = xv * ct + yv * st;
    float yr = -xv * st + yv * ct;
    d_bankU[iu * NT40 + t] = amp * expf(-0.5f * (xr * xr * ip2 + yr * yr * is2));

    if (g < CN) d_biasn[g] = powf(bias[g], nU[g]);
}

// ---------------------------------------------------------------------------
// Kernel 2: per (b,i,tile) — Q[px,t] = P[px,u] · G[t,u]^T via mma.sync tf32
// 128 threads = 4 warps; warp w owns px rows [tile*128 + w*32, +32)
// ---------------------------------------------------------------------------
__global__ __launch_bounds__(128) void mma_kernel(const float* __restrict__ x,
                                                  const float* __restrict__ nI) {
    __shared__ unsigned sB[CN * NT40];   // G[u][t] as tf32 bits, pitch 40
    __shared__ float sNI[CN];

    const int cta  = blockIdx.x;
    const int tile = cta % NTILES;
    const int bi   = cta / NTILES;
    const int i    = bi & (CN - 1);
    const int tid  = threadIdx.x;
    const int w    = tid >> 5;
    const int lane = tid & 31;
    const int lk   = lane & 3;           // thread-in-group (K / col idx)
    const int lg   = lane >> 2;          // group (row idx)

    // fill B: 5120 elements, float4-vectorized, cvt.rna -> tf32
    const float* bu = d_bankU + i * CN * NT40;
    for (int e = tid; e < CN * NT40 / 4; e += 128) {
        float4 v = *(const float4*)(bu + 4 * e);
        sB[4 * e + 0] = cvt_tf32(v.x);
        sB[4 * e + 1] = cvt_tf32(v.y);
        sB[4 * e + 2] = cvt_tf32(v.z);
        sB[4 * e + 3] = cvt_tf32(v.w);
    }
    if (tid < CN) sNI[tid] = nI[i * CN + tid];

    // per-thread log2(x) at its 4 fragment rows (lanes in a group share -> bcast)
    const int pxb = tile * TILE_M + w * 32;
    float L[4];
    #pragma unroll
    for (int rr = 0; rr < 4; rr++) {
        int px = pxb + lg + 8 * rr;
        L[rr] = (px < NPX) ? fast_lg2(x[bi * NPX + px]) : 0.0f;
    }
    __syncthreads();

    float acc[2][5][4];
    #pragma unroll
    for (int mt = 0; mt < 2; mt++)
        #pragma unroll
        for (int nt = 0; nt < 5; nt++)
            #pragma unroll
            for (int q = 0; q < 4; q++) acc[mt][nt][q] = 0.0f;

    #pragma unroll
    for (int kt = 0; kt < 16; kt++) {
        float n0 = sNI[kt * 8 + lk];
        float n1 = sNI[kt * 8 + lk + 4];
        // A fragments in registers: a[mt] covers rows mt*16 + {lg, lg+8}
        unsigned a[2][4];
        #pragma unroll
        for (int mt = 0; mt < 2; mt++) {
            a[mt][0] = cvt_tf32(fast_ex2(n0 * L[2 * mt + 0]));
            a[mt][1] = cvt_tf32(fast_ex2(n0 * L[2 * mt + 1]));
            a[mt][2] = cvt_tf32(fast_ex2(n1 * L[2 * mt + 0]));
            a[mt][3] = cvt_tf32(fast_ex2(n1 * L[2 * mt + 1]));
        }
        #pragma unroll
        for (int nt = 0; nt < 5; nt++) {
            unsigned b0 = sB[(kt * 8 + lk) * NT40 + nt * 8 + lg];
            unsigned b1 = sB[(kt * 8 + lk + 4) * NT40 + nt * 8 + lg];
            mma8(acc[0][nt], a[0], b0, b1);
            mma8(acc[1][nt], a[1], b0, b1);
        }
    }

    // store D -> Q[bi][t][px]; writes into px pad region (3136..3199) are
    // harmless (never read by gather)
    float* q = d_Q + (size_t)bi * NT40 * QPITCH;
    #pragma unroll
    for (int mt = 0; mt < 2; mt++) {
        int r_lo = pxb + mt * 16 + lg;
        int r_hi = r_lo + 8;
        #pragma unroll
        for (int nt = 0; nt < 5; nt++) {
            int t0 = nt * 8 + lk * 2;
            q[(size_t)t0 * QPITCH + r_lo]       = acc[mt][nt][0];
            q[(size_t)(t0 + 1) * QPITCH + r_lo] = acc[mt][nt][1];
            q[(size_t)t0 * QPITCH + r_hi]       = acc[mt][nt][2];
            q[(size_t)(t0 + 1) * QPITCH + r_hi] = acc[mt][nt][3];
        }
    }
}

// ---------------------------------------------------------------------------
// Kernel 3: shift-gather over 36 taps + combine
// out = x^nU / (bias^nU + sum_t Q[t][shifted])
// ---------------------------------------------------------------------------
__global__ void gather_kernel(const float* __restrict__ x,
                              const float* __restrict__ nU,
                              float* __restrict__ out, int total) {
    int idx = blockIdx.x * blockDim.x + threadIdx.x;
    if (idx >= total) return;
    int px = idx % NPX;
    int bi = idx / NPX;
    int i  = bi & (CN - 1);
    int y  = px / SS;
    int xx = px - y * SS;

    const float* q = d_Q + (size_t)bi * NT40 * QPITCH;
    float sum = 0.0f;
    #pragma unroll
    for (int r = 0; r < 6; r++) {
        int yy = y + r - 2;
        if ((unsigned)yy < SS) {
            #pragma unroll
            for (int c = 0; c < 6; c++) {
                int xc = xx + c - 2;
                if ((unsigned)xc < SS)
                    sum += q[(size_t)(r * 6 + c) * QPITCH + yy * SS + xc];
            }
        }
    }
    float num = fast_ex2(nU[i] * fast_lg2(x[idx]));
    out[idx] = num / (d_biasn[i] + sum);
}

// ---------------------------------------------------------------------------
extern "C" void kernel_launch(void* const* d_in, const int* in_sizes, int n_in,
                              void* d_out, int out_size) {
    const float* x     = (const float*)d_in[0];
    const float* theta = (const float*)d_in[1];
    const float* p     = (const float*)d_in[2];
    const float* sig   = (const float*)d_in[3];
    const float* a     = (const float*)d_in[4];
    const float* nI    = (const float*)d_in[5];
    const float* nU    = (const float*)d_in[6];
    const float* bias  = (const float*)d_in[7];
    float* out = (float*)d_out;

    int B = in_sizes[0] / (CN * NPX);   // = 2

    bank_kernel<<<(CN * CN * NTAP + 255) / 256, 256>>>(theta, p, sig, a, bias, nU);
    mma_kernel<<<B * CN * NTILES, 128>>>(x, nI);
    gather_kernel<<<(out_size + 255) / 256, 256>>>(x, nU, out, out_size);
}